// round 1
// baseline (speedup 1.0000x reference)
#include <cuda_runtime.h>
#include <cuda_bf16.h>
#include <cstdint>

// Batched complex QR (Q only), LAPACK Householder convention.
//   Input : x [B, 64, 16, 2] float32 (re/im interleaved last dim)
//   Output: q [B, 64, 16, 2] float32
//
// One warp per matrix. Lane L owns rows L and L+32.
// Phase 1: Householder elimination (geqrf) in registers -> R (distributed,
//          row i of R lives in lane i's working copy), betas broadcast.
// Phase 2: Q = X * R^-1 via column back-substitution on the preserved
//          original X (no reductions needed).

#define NR 16
#define NM 64

__global__ void __launch_bounds__(128, 1)
qr_householder_kernel(const float* __restrict__ in,
                      float* __restrict__ out,
                      int B)
{
    const int warp = threadIdx.x >> 5;
    const int lane = threadIdx.x & 31;
    const long long b = (long long)blockIdx.x * 4 + warp;
    if (b >= B) return;

    const unsigned FULL = 0xffffffffu;

    // ---- load: rows lane and lane+32, 32 floats each (contiguous) ----
    const float* src = in + b * (long long)(NM * NR * 2);
    float2 x1[NR], x2[NR];   // original matrix (kept for back-substitution)
    float2 a1[NR], a2[NR];   // working copy (destroyed into R + reflectors)
    {
        const float4* p1 = (const float4*)(src + (size_t)lane * (NR * 2));
        const float4* p2 = (const float4*)(src + (size_t)(lane + 32) * (NR * 2));
#pragma unroll
        for (int i = 0; i < 8; i++) {
            float4 t = p1[i];
            x1[2 * i]     = make_float2(t.x, t.y);
            x1[2 * i + 1] = make_float2(t.z, t.w);
            t = p2[i];
            x2[2 * i]     = make_float2(t.x, t.y);
            x2[2 * i + 1] = make_float2(t.z, t.w);
        }
#pragma unroll
        for (int k = 0; k < NR; k++) { a1[k] = x1[k]; a2[k] = x2[k]; }
    }

    float beta[NR];   // real diagonal of R (lane-uniform)

    // ================= Householder elimination (cgeqrf) =================
#pragma unroll
    for (int j = 0; j < NR; j++) {
        // alpha = A[j][j] (row j is lane j's "row1")
        const float are = __shfl_sync(FULL, a1[j].x, j);
        const float aim = __shfl_sync(FULL, a1[j].y, j);

        // squared norm of the strictly-below-diagonal part of column j
        float t = a2[j].x * a2[j].x + a2[j].y * a2[j].y;   // row lane+32 (>j always)
        if (lane > j) t += a1[j].x * a1[j].x + a1[j].y * a1[j].y;
#pragma unroll
        for (int s = 16; s > 0; s >>= 1) t += __shfl_xor_sync(FULL, t, s);

        float bet, idr, idi, ctr, cti;
        if (t == 0.0f && aim == 0.0f) {
            // clarfg degenerate path: tau = 0, H = I, R[j][j] = alpha
            bet = are; idr = 0.f; idi = 0.f; ctr = 0.f; cti = 0.f;
        } else {
            const float nrm = sqrtf(are * are + aim * aim + t);  // lapy3
            bet = (are >= 0.0f) ? -nrm : nrm;                    // -sign(Re(alpha))*nrm
            // 1/(alpha - beta)
            const float dr = are - bet, di = aim;
            const float dd = 1.0f / (dr * dr + di * di);
            idr = dr * dd; idi = -di * dd;
            // conj(tau), tau = (beta - alpha)/beta  (beta real)
            const float ib = 1.0f / bet;
            ctr = (bet - are) * ib;
            cti = aim * ib;
        }
        beta[j] = bet;

        // reflector v (v[j] = 1, zero above j)
        float v1r, v1i;
        const float v2r = a2[j].x * idr - a2[j].y * idi;
        const float v2i = a2[j].x * idi + a2[j].y * idr;
        if (lane > j)       { v1r = a1[j].x * idr - a1[j].y * idi;
                              v1i = a1[j].x * idi + a1[j].y * idr; }
        else if (lane == j) { v1r = 1.0f; v1i = 0.0f; }
        else                { v1r = 0.0f; v1i = 0.0f; }

        // R diagonal into the distributed R storage
        if (lane == j) { a1[j].x = bet; a1[j].y = 0.0f; }

        // w_k = v^H a_k for all trailing columns (batched butterfly reduce)
        float wr[NR], wi[NR];
#pragma unroll
        for (int k = j + 1; k < NR; k++) {
            wr[k] = v1r * a1[k].x + v1i * a1[k].y + v2r * a2[k].x + v2i * a2[k].y;
            wi[k] = v1r * a1[k].y - v1i * a1[k].x + v2r * a2[k].y - v2i * a2[k].x;
        }
#pragma unroll
        for (int s = 16; s > 0; s >>= 1) {
#pragma unroll
            for (int k = j + 1; k < NR; k++) {
                wr[k] += __shfl_xor_sync(FULL, wr[k], s);
                wi[k] += __shfl_xor_sync(FULL, wi[k], s);
            }
        }
        // a_k -= conj(tau) * w_k * v   (rows >= j only; v is zero above)
#pragma unroll
        for (int k = j + 1; k < NR; k++) {
            const float cr = ctr * wr[k] - cti * wi[k];
            const float ci = ctr * wi[k] + cti * wr[k];
            a1[k].x -= cr * v1r - ci * v1i;
            a1[k].y -= cr * v1i + ci * v1r;
            a2[k].x -= cr * v2r - ci * v2i;
            a2[k].y -= cr * v2i + ci * v2r;
        }
    }

    // ================= Q = X * R^{-1} (back-substitution) =================
    // q_k = (x_k - sum_{i<k} R[i][k] * q_i) / beta_k   (in place over x)
#pragma unroll
    for (int k = 0; k < NR; k++) {
#pragma unroll
        for (int i = 0; i < k; i++) {
            const float rr = __shfl_sync(FULL, a1[k].x, i);   // R[i][k]
            const float ri = __shfl_sync(FULL, a1[k].y, i);
            x1[k].x -= rr * x1[i].x - ri * x1[i].y;
            x1[k].y -= rr * x1[i].y + ri * x1[i].x;
            x2[k].x -= rr * x2[i].x - ri * x2[i].y;
            x2[k].y -= rr * x2[i].y + ri * x2[i].x;
        }
        const float ib = 1.0f / beta[k];
        x1[k].x *= ib; x1[k].y *= ib;
        x2[k].x *= ib; x2[k].y *= ib;
    }

    // ---- store ----
    float* dst = out + b * (long long)(NM * NR * 2);
    float4* o1 = (float4*)(dst + (size_t)lane * (NR * 2));
    float4* o2 = (float4*)(dst + (size_t)(lane + 32) * (NR * 2));
#pragma unroll
    for (int i = 0; i < 8; i++) {
        o1[i] = make_float4(x1[2 * i].x, x1[2 * i].y, x1[2 * i + 1].x, x1[2 * i + 1].y);
        o2[i] = make_float4(x2[2 * i].x, x2[2 * i].y, x2[2 * i + 1].x, x2[2 * i + 1].y);
    }
}

extern "C" void kernel_launch(void* const* d_in, const int* in_sizes, int n_in,
                              void* d_out, int out_size)
{
    const float* x = (const float*)d_in[0];
    float* q = (float*)d_out;
    const int B = in_sizes[0] / (NM * NR * 2);   // 32768
    const int warps_per_block = 4;
    const int grid = (B + warps_per_block - 1) / warps_per_block;
    qr_householder_kernel<<<grid, warps_per_block * 32>>>(x, q, B);
}

// round 2
// speedup vs baseline: 1.1233x; 1.1233x over previous
#include <cuda_runtime.h>
#include <cuda_bf16.h>
#include <cstdint>

// Batched complex QR (Q only), LAPACK Householder convention.
//   Input : x [B, 64, 16, 2] float32   Output: q [B, 64, 16, 2] float32
//
// One warp per matrix; lane L owns rows L and L+32.
// Register-pressure-optimized: original X staged in SMEM (transposed),
// working copy A in registers (destroyed into R + reflectors), Q formed by
// back-substitution Q = X R^{-1} reading X columns from SMEM.

#define NR 16
#define NM 64
#define WPB 4   // warps per block

__global__ void __launch_bounds__(128, 4)
qr_householder_kernel(const float* __restrict__ in,
                      float* __restrict__ out,
                      int B)
{
    // [warp][col][row] : column reads are lane-contiguous -> conflict-free.
    __shared__ float2 sx[WPB][NR][NM];   // 4*16*64*8 = 32 KB

    const int warp = threadIdx.x >> 5;
    const int lane = threadIdx.x & 31;
    const long long b = (long long)blockIdx.x * WPB + warp;
    if (b >= B) return;

    const unsigned FULL = 0xffffffffu;

    // ---- load rows lane and lane+32 (coalesced float4), stage X to smem ----
    const float* src = in + b * (long long)(NM * NR * 2);
    float2 a1[NR], a2[NR];   // working copy -> becomes R (upper) + reflectors
    {
        const float4* p1 = (const float4*)(src + (size_t)lane * (NR * 2));
        const float4* p2 = (const float4*)(src + (size_t)(lane + 32) * (NR * 2));
#pragma unroll
        for (int i = 0; i < 8; i++) {
            float4 t = p1[i];
            a1[2 * i]     = make_float2(t.x, t.y);
            a1[2 * i + 1] = make_float2(t.z, t.w);
            t = p2[i];
            a2[2 * i]     = make_float2(t.x, t.y);
            a2[2 * i + 1] = make_float2(t.z, t.w);
        }
#pragma unroll
        for (int k = 0; k < NR; k++) {
            sx[warp][k][lane]      = a1[k];
            sx[warp][k][lane + 32] = a2[k];
        }
    }

    // ================= Householder elimination (cgeqrf) =================
#pragma unroll
    for (int j = 0; j < NR; j++) {
        const float are = __shfl_sync(FULL, a1[j].x, j);
        const float aim = __shfl_sync(FULL, a1[j].y, j);

        // squared norm of strictly-below-diagonal part of column j
        float t = a2[j].x * a2[j].x + a2[j].y * a2[j].y;
        if (lane > j) t += a1[j].x * a1[j].x + a1[j].y * a1[j].y;
#pragma unroll
        for (int s = 16; s > 0; s >>= 1) t += __shfl_xor_sync(FULL, t, s);

        float bet, idr, idi, ctr, cti;
        if (t == 0.0f && aim == 0.0f) {
            bet = are; idr = 0.f; idi = 0.f; ctr = 0.f; cti = 0.f; // tau=0 path
        } else {
            const float nrm = sqrtf(are * are + aim * aim + t);
            bet = (are >= 0.0f) ? -nrm : nrm;        // -sign(Re(alpha))*nrm
            const float dr = are - bet, di = aim;    // 1/(alpha-beta)
            const float dd = __fdividef(1.0f, dr * dr + di * di);
            idr = dr * dd; idi = -di * dd;
            const float ib = __fdividef(1.0f, bet);  // conj(tau)
            ctr = (bet - are) * ib;
            cti = aim * ib;
        }

        // reflector v (v[j]=1, zero above j)
        float v1r, v1i;
        const float v2r = a2[j].x * idr - a2[j].y * idi;
        const float v2i = a2[j].x * idi + a2[j].y * idr;
        if (lane > j)       { v1r = a1[j].x * idr - a1[j].y * idi;
                              v1i = a1[j].x * idi + a1[j].y * idr; }
        else if (lane == j) { v1r = 1.0f; v1i = 0.0f; }
        else                { v1r = 0.0f; v1i = 0.0f; }

        // R diagonal (beta) into distributed R storage
        if (lane == j) { a1[j].x = bet; a1[j].y = 0.0f; }

        // w_k = v^H a_k for trailing columns (batched butterfly reduction)
        float wr[NR], wi[NR];
#pragma unroll
        for (int k = j + 1; k < NR; k++) {
            wr[k] = v1r * a1[k].x + v1i * a1[k].y + v2r * a2[k].x + v2i * a2[k].y;
            wi[k] = v1r * a1[k].y - v1i * a1[k].x + v2r * a2[k].y - v2i * a2[k].x;
        }
#pragma unroll
        for (int s = 16; s > 0; s >>= 1) {
#pragma unroll
            for (int k = j + 1; k < NR; k++) {
                wr[k] += __shfl_xor_sync(FULL, wr[k], s);
                wi[k] += __shfl_xor_sync(FULL, wi[k], s);
            }
        }
        // rank-1 update: a_k -= conj(tau) * w_k * v
#pragma unroll
        for (int k = j + 1; k < NR; k++) {
            const float cr = ctr * wr[k] - cti * wi[k];
            const float ci = ctr * wi[k] + cti * wr[k];
            a1[k].x -= cr * v1r - ci * v1i;
            a1[k].y -= cr * v1i + ci * v1r;
            a2[k].x -= cr * v2r - ci * v2i;
            a2[k].y -= cr * v2i + ci * v2r;
        }
    }

    // ================= Q = X * R^{-1} (back-substitution) =================
    // q_k = (x_k - sum_{i<k} R[i][k] * q_i) / beta_k
    float2 q1[NR], q2[NR];   // reuses a2's register budget (a2 is dead here)
#pragma unroll
    for (int k = 0; k < NR; k++) {
        float2 y1 = sx[warp][k][lane];
        float2 y2 = sx[warp][k][lane + 32];
#pragma unroll
        for (int i = 0; i < k; i++) {
            const float rr = __shfl_sync(FULL, a1[k].x, i);   // R[i][k]
            const float ri = __shfl_sync(FULL, a1[k].y, i);
            y1.x -= rr * q1[i].x - ri * q1[i].y;
            y1.y -= rr * q1[i].y + ri * q1[i].x;
            y2.x -= rr * q2[i].x - ri * q2[i].y;
            y2.y -= rr * q2[i].y + ri * q2[i].x;
        }
        const float bet = __shfl_sync(FULL, a1[k].x, k);      // beta_k
        const float ib = __fdividef(1.0f, bet);
        y1.x *= ib; y1.y *= ib;
        y2.x *= ib; y2.y *= ib;
        q1[k] = y1; q2[k] = y2;
    }

    // ---- store (coalesced float4) ----
    float* dst = out + b * (long long)(NM * NR * 2);
    float4* o1 = (float4*)(dst + (size_t)lane * (NR * 2));
    float4* o2 = (float4*)(dst + (size_t)(lane + 32) * (NR * 2));
#pragma unroll
    for (int i = 0; i < 8; i++) {
        o1[i] = make_float4(q1[2 * i].x, q1[2 * i].y, q1[2 * i + 1].x, q1[2 * i + 1].y);
        o2[i] = make_float4(q2[2 * i].x, q2[2 * i].y, q2[2 * i + 1].x, q2[2 * i + 1].y);
    }
}

extern "C" void kernel_launch(void* const* d_in, const int* in_sizes, int n_in,
                              void* d_out, int out_size)
{
    const float* x = (const float*)d_in[0];
    float* q = (float*)d_out;
    const int B = in_sizes[0] / (NM * NR * 2);   // 32768
    const int grid = (B + WPB - 1) / WPB;
    qr_householder_kernel<<<grid, WPB * 32>>>(x, q, B);
}

// round 4
// speedup vs baseline: 1.1759x; 1.0468x over previous
#include <cuda_runtime.h>
#include <cuda_bf16.h>
#include <cstdint>

// Batched complex QR (Q only), LAPACK Householder convention.
//   Input : x [B, 64, 16, 2] float32   Output: q [B, 64, 16, 2] float32
//
// TWO matrices per warp: 16-lane groups, lane owns 4 rows (l, l+16, l+32, l+48).
// Butterfly reductions are 4 steps and serve both matrices per instruction.
// X staged in padded SMEM (coalesced global I/O + phase-2 column reads);
// R published to SMEM once, read back as uniform broadcasts.

#define NR   16
#define WPB  4            // warps per block
#define MPB  (WPB * 2)    // matrices per block
#define ROWP 17           // padded row length in float2 (bank-conflict-free)

#define SX_F2 (MPB * 64 * ROWP)     // 8704 float2
#define SR_F2 (MPB * 256)           // 2048 float2
#define SMEM_BYTES ((SX_F2 + SR_F2) * (int)sizeof(float2))   // 86016

__global__ void __launch_bounds__(128, 2)
qr_householder_kernel(const float* __restrict__ in,
                      float* __restrict__ out,
                      int B)
{
    extern __shared__ float2 smem[];
    float2* sx = smem;             // [MPB][64][ROWP]
    float2* sR = smem + SX_F2;     // [MPB][16][16]  sR[m][k][i] = R[i][k]

    const int tid  = threadIdx.x;
    const int warp = tid >> 5;
    const int lane = tid & 31;
    const int g    = lane >> 4;    // group (matrix) within warp
    const int l    = lane & 15;    // lane within group
    const int mw   = warp * 2;     // first matrix index of this warp in block
    const long long b0 = (long long)blockIdx.x * MPB;
    if (b0 + mw >= B) return;

    const unsigned FULL = 0xffffffffu;

    // ---- coalesced load of this warp's 2 matrices -> padded SMEM ----
    {
        const float4* src = (const float4*)(in + (b0 + mw) * 2048);
#pragma unroll
        for (int i = 0; i < 32; i++) {
            const int idx = i * 32 + lane;          // 0..1023 float4 units
            const float4 v = src[idx];
            const int m   = idx >> 9;
            const int rem = idx & 511;
            const int row = rem >> 3;
            const int cp  = rem & 7;
            float2* p = sx + ((mw + m) * 64 * ROWP + row * ROWP + cp * 2);
            p[0] = make_float2(v.x, v.y);
            p[1] = make_float2(v.z, v.w);
        }
    }
    __syncwarp();

    // ---- pull working copy into registers: a[r][k] = row (l+16r), col k ----
    float2* sxm = sx + (mw + g) * 64 * ROWP;
    float2* sRm = sR + (mw + g) * 256;
    float2 a[4][NR];
#pragma unroll
    for (int r = 0; r < 4; r++)
#pragma unroll
        for (int k = 0; k < NR; k++)
            a[r][k] = sxm[(l + 16 * r) * ROWP + k];

    // ================= Householder elimination (cgeqrf) =================
#pragma unroll
    for (int j = 0; j < NR; j++) {
        const int srcj = (g << 4) | j;
        const float are = __shfl_sync(FULL, a[0][j].x, srcj);
        const float aim = __shfl_sync(FULL, a[0][j].y, srcj);

        // squared norm of strictly-below-diagonal part of column j
        float t = a[1][j].x * a[1][j].x + a[1][j].y * a[1][j].y
                + a[2][j].x * a[2][j].x + a[2][j].y * a[2][j].y
                + a[3][j].x * a[3][j].x + a[3][j].y * a[3][j].y;
        if (l > j) t += a[0][j].x * a[0][j].x + a[0][j].y * a[0][j].y;
#pragma unroll
        for (int s = 8; s; s >>= 1) t += __shfl_xor_sync(FULL, t, s);

        float bet, idr, idi, ctr, cti;
        if (t == 0.0f && aim == 0.0f) {
            bet = are; idr = 0.f; idi = 0.f; ctr = 0.f; cti = 0.f; // tau=0
        } else {
            const float nrm = sqrtf(are * are + aim * aim + t);
            bet = (are >= 0.0f) ? -nrm : nrm;        // -sign(Re(alpha))*nrm
            const float dr = are - bet, di = aim;    // 1/(alpha-beta)
            const float dd = __fdividef(1.0f, dr * dr + di * di);
            idr = dr * dd; idi = -di * dd;
            const float ib = __fdividef(1.0f, bet);  // conj(tau)
            ctr = (bet - are) * ib;
            cti = aim * ib;
        }

        // reflector v over this lane's 4 rows (v[row j]=1, zero above j)
        float vr[4], vi[4];
#pragma unroll
        for (int r = 1; r < 4; r++) {
            vr[r] = a[r][j].x * idr - a[r][j].y * idi;
            vi[r] = a[r][j].x * idi + a[r][j].y * idr;
        }
        if (l > j)       { vr[0] = a[0][j].x * idr - a[0][j].y * idi;
                           vi[0] = a[0][j].x * idi + a[0][j].y * idr; }
        else if (l == j) { vr[0] = 1.0f; vi[0] = 0.0f; }
        else             { vr[0] = 0.0f; vi[0] = 0.0f; }

        if (l == j) { a[0][j].x = bet; a[0][j].y = 0.0f; }  // R diagonal

        // w_k = v^H a_k  (partials over 4 rows, then 4-step butterfly)
        float wr[NR], wi[NR];
#pragma unroll
        for (int k = j + 1; k < NR; k++) {
            float pr = 0.f, pi = 0.f;
#pragma unroll
            for (int r = 0; r < 4; r++) {
                pr += vr[r] * a[r][k].x + vi[r] * a[r][k].y;
                pi += vr[r] * a[r][k].y - vi[r] * a[r][k].x;
            }
            wr[k] = pr; wi[k] = pi;
        }
#pragma unroll
        for (int s = 8; s; s >>= 1) {
#pragma unroll
            for (int k = j + 1; k < NR; k++) {
                wr[k] += __shfl_xor_sync(FULL, wr[k], s);
                wi[k] += __shfl_xor_sync(FULL, wi[k], s);
            }
        }
        // rank-1 update: a_k -= conj(tau) * w_k * v
#pragma unroll
        for (int k = j + 1; k < NR; k++) {
            const float cr = ctr * wr[k] - cti * wi[k];
            const float ci = ctr * wi[k] + cti * wr[k];
#pragma unroll
            for (int r = 0; r < 4; r++) {
                a[r][k].x -= cr * vr[r] - ci * vi[r];
                a[r][k].y -= cr * vi[r] + ci * vr[r];
            }
        }
    }

    // ---- publish R: lane l holds final row l of R in a[0][k], k >= l ----
#pragma unroll
    for (int k = 0; k < NR; k++)
        if (l <= k) sRm[k * 16 + l] = a[0][k];
    __syncwarp();

    // ================= Q = X * R^{-1} (back-substitution) =================
    float2 q[4][NR];
#pragma unroll
    for (int k = 0; k < NR; k++) {
        float2 y[4];
#pragma unroll
        for (int r = 0; r < 4; r++) y[r] = sxm[(l + 16 * r) * ROWP + k];
#pragma unroll
        for (int i = 0; i < k; i++) {
            const float2 rc = sRm[k * 16 + i];     // uniform broadcast
#pragma unroll
            for (int r = 0; r < 4; r++) {
                y[r].x -= rc.x * q[r][i].x - rc.y * q[r][i].y;
                y[r].y -= rc.x * q[r][i].y + rc.y * q[r][i].x;
            }
        }
        const float ib = __fdividef(1.0f, sRm[k * 16 + k].x);  // 1/beta_k
#pragma unroll
        for (int r = 0; r < 4; r++) {
            y[r].x *= ib; y[r].y *= ib;
            q[r][k] = y[r];
        }
    }
    __syncwarp();   // all lanes done reading X before overwrite

    // ---- stage Q back into sx, then coalesced store ----
#pragma unroll
    for (int r = 0; r < 4; r++)
#pragma unroll
        for (int k = 0; k < NR; k++)
            sxm[(l + 16 * r) * ROWP + k] = q[r][k];
    __syncwarp();

    {
        float4* dst = (float4*)(out + (b0 + mw) * 2048);
#pragma unroll
        for (int i = 0; i < 32; i++) {
            const int idx = i * 32 + lane;          // 0..1023 float4 units
            const int m   = idx >> 9;
            const int rem = idx & 511;
            const int row = rem >> 3;
            const int cp  = rem & 7;
            const float2* p = sx + ((mw + m) * 64 * ROWP + row * ROWP + cp * 2);
            const float2 v0 = p[0];
            const float2 v1 = p[1];
            dst[idx] = make_float4(v0.x, v0.y, v1.x, v1.y);
        }
    }
}

extern "C" void kernel_launch(void* const* d_in, const int* in_sizes, int n_in,
                              void* d_out, int out_size)
{
    const float* x = (const float*)d_in[0];
    float* q = (float*)d_out;
    const int B = in_sizes[0] / (64 * NR * 2);   // 32768

    static int smem_set = 0;
    cudaFuncSetAttribute(qr_householder_kernel,
                         cudaFuncAttributeMaxDynamicSharedMemorySize,
                         SMEM_BYTES);
    (void)smem_set;

    const int grid = (B + MPB - 1) / MPB;
    qr_householder_kernel<<<grid, WPB * 32, SMEM_BYTES>>>(x, q, B);
}

// round 5
// speedup vs baseline: 4.0153x; 3.4147x over previous
#include <cuda_runtime.h>
#include <cuda_bf16.h>
#include <cstdint>

// Batched complex QR (Q only), LAPACK Householder convention.
//   Input : x [B, 64, 16, 2] float32   Output: q [B, 64, 16, 2] float32
//
// Two matrices per warp (16-lane groups, lane owns rows l, l+16, l+32, l+48).
// Single fused butterfly per elimination step (tail-norm + all tail dot
// products u_k reduced together); w_k = a[j][k] + conj(inv)*u_k.
// All heavy arithmetic in packed fma.rn.f32x2 (re/im planes, column pairs).

typedef unsigned long long u64;
#define NR   16
#define WPB  4
#define MPB  (WPB * 2)
#define ROWP 17
#define SX_F2 (MPB * 64 * ROWP)
#define SR_F2 (MPB * 136)
#define SMEM_BYTES ((SX_F2 + SR_F2) * (int)sizeof(float2))
#define FULLM 0xffffffffu

__device__ __forceinline__ u64 PK(float lo, float hi) {
    u64 r; asm("mov.b64 %0,{%1,%2};" : "=l"(r) : "f"(lo), "f"(hi)); return r;
}
__device__ __forceinline__ void UPK(u64 v, float& lo, float& hi) {
    asm("mov.b64 {%0,%1},%2;" : "=f"(lo), "=f"(hi) : "l"(v));
}
__device__ __forceinline__ u64 DUP(float x) { return PK(x, x); }
__device__ __forceinline__ u64 FMA2(u64 a, u64 b, u64 c) {
    u64 d; asm("fma.rn.f32x2 %0,%1,%2,%3;" : "=l"(d) : "l"(a), "l"(b), "l"(c)); return d;
}
__device__ __forceinline__ u64 MUL2(u64 a, u64 b) {
    u64 d; asm("mul.rn.f32x2 %0,%1,%2;" : "=l"(d) : "l"(a), "l"(b)); return d;
}
__device__ __forceinline__ u64 ADD2(u64 a, u64 b) {
    u64 d; asm("add.rn.f32x2 %0,%1,%2;" : "=l"(d) : "l"(a), "l"(b)); return d;
}
__device__ __forceinline__ u64 SHX2(u64 v, int s) {
    float a, b; UPK(v, a, b);
    a = __shfl_xor_sync(FULLM, a, s);
    b = __shfl_xor_sync(FULLM, b, s);
    return PK(a, b);
}
__device__ __forceinline__ u64 SHI2(u64 v, int src) {
    float a, b; UPK(v, a, b);
    a = __shfl_sync(FULLM, a, src);
    b = __shfl_sync(FULLM, b, src);
    return PK(a, b);
}

__global__ void __launch_bounds__(128, 2)
qr_householder_kernel(const float* __restrict__ in,
                      float* __restrict__ out,
                      int B)
{
    extern __shared__ float2 smem[];
    float2* sx = smem;             // [MPB][64][ROWP]
    float2* sR = smem + SX_F2;     // packed upper triangles, 136 per matrix

    const int tid  = threadIdx.x;
    const int warp = tid >> 5;
    const int lane = tid & 31;
    const int g    = lane >> 4;
    const int l    = lane & 15;
    const int mw   = warp * 2;
    const long long b0 = (long long)blockIdx.x * MPB;
    if (b0 + mw >= B) return;

    // ---- coalesced load of this warp's 2 matrices -> padded SMEM ----
    {
        const float4* src = (const float4*)(in + (b0 + mw) * 2048);
#pragma unroll
        for (int i = 0; i < 32; i++) {
            const int idx = i * 32 + lane;
            const float4 v = src[idx];
            const int m   = idx >> 9;
            const int rem = idx & 511;
            const int row = rem >> 3;
            const int cp  = rem & 7;
            float2* p = sx + ((mw + m) * 64 * ROWP + row * ROWP + cp * 2);
            p[0] = make_float2(v.x, v.y);
            p[1] = make_float2(v.z, v.w);
        }
    }
    __syncwarp();

    float2* sxm = sx + (mw + g) * 64 * ROWP;
    float2* sRm = sR + (mw + g) * 136;

    // ---- working copy, packed planes: column pair p = cols (2p, 2p+1) ----
    u64 are[4][8], aim[4][8];
#pragma unroll
    for (int r = 0; r < 4; r++)
#pragma unroll
        for (int p = 0; p < 8; p++) {
            const float2 c0 = sxm[(l + 16 * r) * ROWP + 2 * p];
            const float2 c1 = sxm[(l + 16 * r) * ROWP + 2 * p + 1];
            are[r][p] = PK(c0.x, c1.x);
            aim[r][p] = PK(c0.y, c1.y);
        }

    // ================= Householder elimination (cgeqrf) =================
#pragma unroll
    for (int j = 0; j < NR; j++) {
        const int jp   = j >> 1;
        const int srcj = (g << 4) | j;

        // extract column j (unchanged this step until update)
        float xr[4], xi[4];
#pragma unroll
        for (int r = 0; r < 4; r++) {
            float lo, hi; UPK(are[r][jp], lo, hi);
            xr[r] = (j & 1) ? hi : lo;
            UPK(aim[r][jp], lo, hi);
            xi[r] = (j & 1) ? hi : lo;
        }
        const float alr = __shfl_sync(FULLM, xr[0], srcj);   // alpha
        const float ali = __shfl_sync(FULLM, xi[0], srcj);
        const float x0r = (l > j) ? xr[0] : 0.f;
        const float x0i = (l > j) ? xi[0] : 0.f;

        // tail-norm partial
        float t = xr[1]*xr[1] + xi[1]*xi[1] + xr[2]*xr[2] + xi[2]*xi[2]
                + xr[3]*xr[3] + xi[3]*xi[3] + x0r*x0r + x0i*x0i;

        // u_k = sum_tail conj(x) * a_k   (packed partials)
        u64 ur[8], ui[8];
        {
            const u64 X1 = DUP(xr[1]), Y1 = DUP(xi[1]), nY1 = DUP(-xi[1]);
            const u64 X2 = DUP(xr[2]), Y2 = DUP(xi[2]), nY2 = DUP(-xi[2]);
            const u64 X3 = DUP(xr[3]), Y3 = DUP(xi[3]), nY3 = DUP(-xi[3]);
            const u64 X0 = DUP(x0r),   Y0 = DUP(x0i),   nY0 = DUP(-x0i);
#pragma unroll
            for (int p = 0; p < 8; p++) {
                if (2 * p + 1 <= j) continue;
                u64 r_ = FMA2(X1, are[1][p], MUL2(Y1,  aim[1][p]));
                u64 i_ = FMA2(X1, aim[1][p], MUL2(nY1, are[1][p]));
                r_ = FMA2(X2, are[2][p], FMA2(Y2,  aim[2][p], r_));
                i_ = FMA2(X2, aim[2][p], FMA2(nY2, are[2][p], i_));
                r_ = FMA2(X3, are[3][p], FMA2(Y3,  aim[3][p], r_));
                i_ = FMA2(X3, aim[3][p], FMA2(nY3, are[3][p], i_));
                r_ = FMA2(X0, are[0][p], FMA2(Y0,  aim[0][p], r_));
                i_ = FMA2(X0, aim[0][p], FMA2(nY0, are[0][p], i_));
                ur[p] = r_; ui[p] = i_;
            }
        }

        // single fused butterfly: t + all u_k
#pragma unroll
        for (int s = 8; s; s >>= 1) {
            t += __shfl_xor_sync(FULLM, t, s);
#pragma unroll
            for (int p = 0; p < 8; p++) {
                if (2 * p + 1 <= j) continue;
                ur[p] = ADD2(ur[p], SHX2(ur[p], s));
                ui[p] = ADD2(ui[p], SHX2(ui[p], s));
            }
        }

        // Householder scalars (LAPACK clarfg convention)
        float bet, idr, idi, ctr, cti;
        if (t == 0.f && ali == 0.f) {
            bet = alr; idr = 0.f; idi = 0.f; ctr = 0.f; cti = 0.f;  // tau = 0
        } else {
            const float nrm = sqrtf(alr * alr + ali * ali + t);
            bet = (alr >= 0.f) ? -nrm : nrm;
            const float dr = alr - bet, di = ali;
            const float dd = __fdividef(1.f, dr * dr + di * di);
            idr = dr * dd; idi = -di * dd;            // 1/(alpha-beta)
            const float ib = __fdividef(1.f, bet);
            ctr = (bet - alr) * ib; cti = ali * ib;   // conj(tau)
        }

        // reflector v over this lane's rows
        float vr0, vi0;
        if (l > j)       { vr0 = idr*xr[0] - idi*xi[0]; vi0 = idr*xi[0] + idi*xr[0]; }
        else if (l == j) { vr0 = 1.f; vi0 = 0.f; }
        else             { vr0 = 0.f; vi0 = 0.f; }
        const float vr1 = idr*xr[1] - idi*xi[1], vi1 = idr*xi[1] + idi*xr[1];
        const float vr2 = idr*xr[2] - idi*xi[2], vi2 = idr*xi[2] + idi*xr[2];
        const float vr3 = idr*xr[3] - idi*xi[3], vi3 = idr*xi[3] + idi*xr[3];
        const u64 V0r = DUP(vr0), V0i = DUP(vi0), V1r = DUP(vr1), V1i = DUP(vi1);
        const u64 V2r = DUP(vr2), V2i = DUP(vi2), V3r = DUP(vr3), V3i = DUP(vi3);
        const u64 IDR = DUP(idr), IDI = DUP(idi), nIDI = DUP(-idi);
        const u64 CTR = DUP(ctr), nCTR = DUP(-ctr), CTI = DUP(cti), nCTI = DUP(-cti);

        // streamed per pair: row-j broadcast, w = ajk + conj(inv)*u, g = ctau*w,
        // update a -= g * v
#pragma unroll
        for (int p = 0; p < 8; p++) {
            if (2 * p + 1 <= j) continue;
            const u64 ajr = SHI2(are[0][p], srcj);
            const u64 aji = SHI2(aim[0][p], srcj);
            const u64 wr = FMA2(IDR, ur[p], FMA2(IDI,  ui[p], ajr));
            const u64 wi = FMA2(IDR, ui[p], FMA2(nIDI, ur[p], aji));
            const u64 ngr = FMA2(nCTR, wr, MUL2(CTI,  wi));   // -Re(g)
            const u64 gi  = FMA2(CTR,  wi, MUL2(CTI,  wr));   //  Im(g)
            const u64 ngi = FMA2(nCTR, wi, MUL2(nCTI, wr));   // -Im(g)
            are[0][p] = FMA2(ngr, V0r, FMA2(gi,  V0i, are[0][p]));
            aim[0][p] = FMA2(ngr, V0i, FMA2(ngi, V0r, aim[0][p]));
            are[1][p] = FMA2(ngr, V1r, FMA2(gi,  V1i, are[1][p]));
            aim[1][p] = FMA2(ngr, V1i, FMA2(ngi, V1r, aim[1][p]));
            are[2][p] = FMA2(ngr, V2r, FMA2(gi,  V2i, are[2][p]));
            aim[2][p] = FMA2(ngr, V2i, FMA2(ngi, V2r, aim[2][p]));
            are[3][p] = FMA2(ngr, V3r, FMA2(gi,  V3i, are[3][p]));
            aim[3][p] = FMA2(ngr, V3i, FMA2(ngi, V3r, aim[3][p]));
        }

        // R diagonal (beta, real) on lane j
        if (l == j) {
            float lo, hi;
            UPK(are[0][jp], lo, hi);
            are[0][jp] = (j & 1) ? PK(lo, bet) : PK(bet, hi);
            UPK(aim[0][jp], lo, hi);
            aim[0][jp] = (j & 1) ? PK(lo, 0.f) : PK(0.f, hi);
        }
    }

    // ---- publish R (packed upper triangle): lane l holds row l ----
#pragma unroll
    for (int k = 0; k < NR; k++) {
        if (l <= k) {
            float lo, hi, rr, ri;
            UPK(are[0][k >> 1], lo, hi); rr = (k & 1) ? hi : lo;
            UPK(aim[0][k >> 1], lo, hi); ri = (k & 1) ? hi : lo;
            sRm[(k * (k + 1)) / 2 + l] = make_float2(rr, ri);
        }
    }
    __syncwarp();

    // ========== Q = X * R^{-1} back-substitution (packed row pairs) ==========
    u64 qAr[NR], qAi[NR], qBr[NR], qBi[NR];
#pragma unroll
    for (int k = 0; k < NR; k++) {
        const float2 y0 = sxm[(l     ) * ROWP + k];
        const float2 y1 = sxm[(l + 16) * ROWP + k];
        const float2 y2 = sxm[(l + 32) * ROWP + k];
        const float2 y3 = sxm[(l + 48) * ROWP + k];
        u64 yAr = PK(y0.x, y1.x), yAi = PK(y0.y, y1.y);
        u64 yBr = PK(y2.x, y3.x), yBi = PK(y2.y, y3.y);
#pragma unroll
        for (int i = 0; i < k; i++) {
            const float2 rc = sRm[(k * (k + 1)) / 2 + i];   // R[i][k]
            const u64 nRr = DUP(-rc.x), Ri = DUP(rc.y), nRi = DUP(-rc.y);
            yAr = FMA2(nRr, qAr[i], FMA2(Ri,  qAi[i], yAr));
            yAi = FMA2(nRr, qAi[i], FMA2(nRi, qAr[i], yAi));
            yBr = FMA2(nRr, qBr[i], FMA2(Ri,  qBi[i], yBr));
            yBi = FMA2(nRr, qBi[i], FMA2(nRi, qBr[i], yBi));
        }
        const u64 IB = DUP(__fdividef(1.f, sRm[(k * (k + 1)) / 2 + k].x));
        qAr[k] = MUL2(yAr, IB); qAi[k] = MUL2(yAi, IB);
        qBr[k] = MUL2(yBr, IB); qBi[k] = MUL2(yBi, IB);
    }
    __syncwarp();   // everyone done reading X before overwrite

    // ---- stage Q back into sx ----
#pragma unroll
    for (int k = 0; k < NR; k++) {
        float a0, b0, a1, b1;
        UPK(qAr[k], a0, b0); UPK(qAi[k], a1, b1);
        sxm[(l     ) * ROWP + k] = make_float2(a0, a1);
        sxm[(l + 16) * ROWP + k] = make_float2(b0, b1);
        UPK(qBr[k], a0, b0); UPK(qBi[k], a1, b1);
        sxm[(l + 32) * ROWP + k] = make_float2(a0, a1);
        sxm[(l + 48) * ROWP + k] = make_float2(b0, b1);
    }
    __syncwarp();

    // ---- coalesced store ----
    {
        float4* dst = (float4*)(out + (b0 + mw) * 2048);
#pragma unroll
        for (int i = 0; i < 32; i++) {
            const int idx = i * 32 + lane;
            const int m   = idx >> 9;
            const int rem = idx & 511;
            const int row = rem >> 3;
            const int cp  = rem & 7;
            const float2* p = sx + ((mw + m) * 64 * ROWP + row * ROWP + cp * 2);
            const float2 v0 = p[0];
            const float2 v1 = p[1];
            dst[idx] = make_float4(v0.x, v0.y, v1.x, v1.y);
        }
    }
}

extern "C" void kernel_launch(void* const* d_in, const int* in_sizes, int n_in,
                              void* d_out, int out_size)
{
    const float* x = (const float*)d_in[0];
    float* q = (float*)d_out;
    const int B = in_sizes[0] / (64 * NR * 2);   // 32768

    cudaFuncSetAttribute(qr_householder_kernel,
                         cudaFuncAttributeMaxDynamicSharedMemorySize,
                         SMEM_BYTES);

    const int grid = (B + MPB - 1) / MPB;
    qr_householder_kernel<<<grid, WPB * 32, SMEM_BYTES>>>(x, q, B);
}